// round 16
// baseline (speedup 1.0000x reference)
#include <cuda_runtime.h>
#include <cuda_bf16.h>
#include <cstdint>

#define BATCH 16
#define NCH   21
#define HH_   256
#define WW_   256
#define HW    65536
#define CHW   (NCH*HW)
#define DT    0.1f

// GEMM tiling (bf16 m16n8k16): K = 96 (84 feats + bias + 11 zero), N = 96
#define KT6 6          // k16 tiles
#define NT 12          // n8 tiles
#define ROWS_PER_CTA 8

// ---- scratch (allocation-free: __device__ globals) ----
__device__ float g_na[BATCH*HW];
__device__ float g_nb[BATCH*HW];
__device__ float g_nd[BATCH*HW];

__device__ __forceinline__ float lap12(const float v[9]) {
    return (v[0]+v[2]+v[6]+v[8] + 2.f*(v[1]+v[3]+v[5]+v[7]) - 12.f*v[4]) * (1.f/12.f);
}

// ============================================================
// Kernel P: prefix passthrough copy  out[b][0:12] = x[b][0:12]
// ============================================================
__global__ void prefix_copy(const float* __restrict__ x, float* __restrict__ out) {
    int i  = blockIdx.x * 256 + threadIdx.x;          // float4 index within 12*HW
    int bb = blockIdx.y;
    const float4* src = reinterpret_cast<const float4*>(x + (size_t)bb * CHW);
    float4* dst       = reinterpret_cast<float4*>(out + (size_t)bb * CHW);
    dst[i] = src[i];
}

// ============================================================
// Kernel A: oscillator substep -> scratch new_a/new_b/new_d
// ============================================================
__global__ void osc_step(const float* __restrict__ x,
                         const float* __restrict__ sw, const float* __restrict__ sb,
                         const float* __restrict__ pAlpha, const float* __restrict__ pBeta,
                         const float* __restrict__ pOmega, const float* __restrict__ pK,
                         const float* __restrict__ pKappa) {
    int w = blockIdx.x * 128 + threadIdx.x;
    int h = blockIdx.y;
    int bb = blockIdx.z;
    int p = h * WW_ + w;
    const float* xb = x + (size_t)bb * CHW;

    const bool hu = (h > 0), hd = (h < HH_-1), wl = (w > 0), wr = (w < WW_-1);

    auto L9 = [&](const float* base, float v[9]) {
        const float* r0 = base + (h-1)*WW_;
        const float* r1 = base + h*WW_;
        const float* r2 = base + (h+1)*WW_;
        v[0] = (hu&&wl) ? r0[w-1] : 0.f;
        v[1] = hu       ? r0[w]   : 0.f;
        v[2] = (hu&&wr) ? r0[w+1] : 0.f;
        v[3] = wl       ? r1[w-1] : 0.f;
        v[4] =            r1[w];
        v[5] = wr       ? r1[w+1] : 0.f;
        v[6] = (hd&&wl) ? r2[w-1] : 0.f;
        v[7] = hd       ? r2[w]   : 0.f;
        v[8] = (hd&&wr) ? r2[w+1] : 0.f;
    };

    float va[9];
    L9(xb + 3*HW, va);
    float eroded = va[4];
    if (hu) { eroded = fminf(eroded, va[1]); if (wl) eroded = fminf(eroded, va[0]); if (wr) eroded = fminf(eroded, va[2]); }
    if (wl) eroded = fminf(eroded, va[3]);
    if (wr) eroded = fminf(eroded, va[5]);
    if (hd) { eroded = fminf(eroded, va[7]); if (wl) eroded = fminf(eroded, va[6]); if (wr) eroded = fminf(eroded, va[8]); }
    float lapA = lap12(va);

    float q0 = va[4];
    float q1 = va[4] - eroded;
    float q2 = lapA;
    float q3 = xb[4*HW + p];
    float q4 = xb[5*HW + p];

    float I0 = sw[0]*q0 + sw[1]*q1 + sw[2]*q2 + sw[3]*q3 + sw[4]*q4 + sb[0];
    float I1 = sw[5]*q0 + sw[6]*q1 + sw[7]*q2 + sw[8]*q3 + sw[9]*q4 + sb[1];
    float I2 = sw[10]*q0 + sw[11]*q1 + sw[12]*q2 + sw[13]*q3 + sw[14]*q4 + sb[2];

    float vv[9];
    L9(xb + 15*HW, vv); float av = vv[4], lA = lap12(vv);
    L9(xb + 16*HW, vv); float bv = vv[4], lB = lap12(vv);
    L9(xb + 17*HW, vv); float dv = vv[4], lD = lap12(vv);

    float alpha = pAlpha[0], beta = pBeta[0], omega = pOmega[0], K = pK[0], kap = pKappa[0];

    float na = av + DT * (-alpha*av + omega*bv + K*lA + I0);
    float nb = bv + DT * (-alpha*bv - omega*av + K*lB + I1);
    float nd = dv + DT * (-beta*dv + kap*lD + I2);

    int gi = bb*HW + p;
    g_na[gi] = na; g_nb[gi] = nb; g_nd[gi] = nd;
}

// ============================================================
// Kernel B: avg_pool5 + normalize + correction + phase/amp/mod
// ============================================================
__global__ void osc_post(float* __restrict__ out,
                         const float* __restrict__ mw, const float* __restrict__ mb) {
    int w = blockIdx.x * 128 + threadIdx.x;
    int h = blockIdx.y;
    int bb = blockIdx.z;
    int p = h * WW_ + w;
    int gi = bb*HW + p;

    float sa = 0.f, sb2 = 0.f;
    #pragma unroll
    for (int dy = -2; dy <= 2; dy++) {
        int hh = h + dy;
        if (hh < 0 || hh >= HH_) continue;
        #pragma unroll
        for (int dx = -2; dx <= 2; dx++) {
            int ww = w + dx;
            if (ww < 0 || ww >= WW_) continue;
            int ii = bb*HW + hh*WW_ + ww;
            sa  += g_na[ii];
            sb2 += g_nb[ii];
        }
    }
    float aavg = sa * (1.f/25.f);
    float bavg = sb2 * (1.f/25.f);
    float rho = sqrtf(aavg*aavg + bavg*bavg + 1e-6f);
    aavg /= rho;
    bavg /= rho;

    float na = g_na[gi], nb = g_nb[gi], nd = g_nd[gi];
    float fa = na + DT * (aavg - na);
    float fb = nb + DT * (bavg - nb);

    float phase = sqrtf(fa*fa + fb*fb + 1e-6f);
    float amp = atan2f(fb, fa);

    float m0 = mw[0]*fa + mw[1]*fb + mw[2]*nd + mb[0];
    float m1 = mw[3]*fa + mw[4]*fb + mw[5]*nd + mb[1];
    float m2 = mw[6]*fa + mw[7]*fb + mw[8]*nd + mb[2];

    float* ob = out + (size_t)bb * CHW;
    ob[15*HW + p] = fa;
    ob[16*HW + p] = fb;
    ob[17*HW + p] = nd;
    ob[18*HW + p] = m0;
    ob[19*HW + p] = m1;
    ob[20*HW + p] = m2;

    float* phaseOut = out + (size_t)BATCH * CHW;
    float* ampOut   = phaseOut + (size_t)BATCH * HW;
    phaseOut[gi] = phase;
    ampOut[gi]   = amp;
}

// ============================================================
// Kernel C: perception (wrap) + warp mma.sync bf16 m16n8k16 MLP
// fused both-half GEMM, 45KB smem -> 5 CTAs/SM; prefix stores offloaded
// ============================================================
__device__ __forceinline__ uint32_t pack_bf16(float lo, float hi) {
    uint32_t r;
    asm("cvt.rn.bf16x2.f32 %0, %1, %2;" : "=r"(r) : "f"(hi), "f"(lo));
    return r;
}

#define MMA_BF16(c0,c1,c2,c3, a0,a1,a2,a3, b0,b1) \
    asm volatile("mma.sync.aligned.m16n8k16.row.col.f32.bf16.bf16.f32 " \
        "{%0,%1,%2,%3}, {%4,%5,%6,%7}, {%8,%9}, {%0,%1,%2,%3};" \
        : "+f"(c0), "+f"(c1), "+f"(c2), "+f"(c3) \
        : "r"(a0), "r"(a1), "r"(a2), "r"(a3), "r"(b0), "r"(b1))

// dynamic SMEM layout (bytes)
#define SM_BFRAG 0                       // NT*KT6*32 u64 = 18432
#define SM_W2    18432                   // 96 float4 = 1536
#define SM_Y0    19968                   // 128 float = 512
#define SM_Y1    20480                   // 128 float = 512
#define SM_Y2    20992                   // 128 float = 512
#define SM_A     21504                   // 128 rows x 192B, mod-12 swizzle
#define A_STRIDE 192
#define SM_TOTAL (SM_A + 128*A_STRIDE)   // 46080 = 45KB -> 5 CTAs/SM

// A tile: row r, 16B chunk c in [0,12), byte off within chunk.
// swizzle: sw = (c + 3*((r>>1)&3)) mod 12  -> conflict-free within 8-row groups
__device__ __forceinline__ char* a_addr(char* smem, int r, int c, int byteoff) {
    int swc = c + 3*((r >> 1) & 3);
    swc = (swc >= 12) ? swc - 12 : swc;
    return smem + SM_A + r*A_STRIDE + (swc << 4) + byteoff;
}

// feature row -> w1 source value
__device__ __forceinline__ float w1_feat(const float* __restrict__ w1w,
                                         const float* __restrict__ w1b,
                                         int col, int r) {
    if (r < 84) {
        int cc = r >> 2, j = r & 3;
        return w1w[col*84 + (j == 0 ? cc : 21 + 3*cc + (j-1))];
    }
    return (r == 84) ? w1b[col] : 0.f;
}

__global__ void __launch_bounds__(128, 5) gene_mlp_mma(
    const float* __restrict__ x, const float* __restrict__ rn,
    const float* __restrict__ w1w, const float* __restrict__ w1b,
    const float* __restrict__ w2w, float* __restrict__ out) {

    extern __shared__ __align__(128) char smem[];
    unsigned long long* bfrag = reinterpret_cast<unsigned long long*>(smem + SM_BFRAG);
    float4* w2s = reinterpret_cast<float4*>(smem + SM_W2);
    float* y0buf = reinterpret_cast<float*>(smem + SM_Y0);
    float* y1buf = reinterpret_cast<float*>(smem + SM_Y1);
    float* y2buf = reinterpret_cast<float*>(smem + SM_Y2);

    const int tid  = threadIdx.x;
    const int lane = tid & 31;
    const int warp = tid >> 5;
    const int w4   = lane >> 2;   // 0..7
    const int c4   = lane & 3;    // 0..3

    // ---- stage B fragments (bf16 pairs) once per CTA ----
    for (int i = tid; i < NT*KT6*32; i += 128) {
        int n   = i / (KT6*32);
        int rem = i - n*(KT6*32);
        int k   = rem >> 5;
        int l   = rem & 31;
        int col = 8*n + (l >> 2);
        int kb  = 16*k + 2*(l & 3);
        uint32_t lo = pack_bf16(w1_feat(w1w, w1b, col, kb),
                                w1_feat(w1w, w1b, col, kb + 1));
        uint32_t hi = pack_bf16(w1_feat(w1w, w1b, col, kb + 8),
                                w1_feat(w1w, w1b, col, kb + 9));
        bfrag[i] = (unsigned long long)lo | ((unsigned long long)hi << 32);
    }
    for (int n = tid; n < 96; n += 128)
        w2s[n] = make_float4(w2w[n], w2w[96 + n], w2w[192 + n], 0.f);

    // constant A columns: chunk 10 half1 = (bias=1, 0, 0, 0); chunk 11 = zeros
    {
        uint2 bz; bz.x = pack_bf16(1.f, 0.f); bz.y = pack_bf16(0.f, 0.f);
        *reinterpret_cast<uint2*>(a_addr(smem, tid, 10, 8)) = bz;
        uint2 zz; zz.x = 0u; zz.y = 0u;
        *reinterpret_cast<uint2*>(a_addr(smem, tid, 11, 0)) = zz;
        *reinterpret_cast<uint2*>(a_addr(smem, tid, 11, 8)) = zz;
    }
    __syncthreads();

    const int w  = blockIdx.x * 128 + tid;
    const int bb = blockIdx.z;
    const float* xb = x + (size_t)bb * CHW;
    float* ob = out + (size_t)bb * CHW;

    #pragma unroll 1
    for (int t = 0; t < ROWS_PER_CTA; t++) {
        const int h  = blockIdx.y * ROWS_PER_CTA + t;
        const int hm = (h - 1) & 255, hp = (h + 1) & 255;
        const int wm = (w - 1) & 255, wp = (w + 1) & 255;
        const int p  = h * WW_ + w;

        float g0 = 0.f, g1 = 0.f, g2 = 0.f, life = 0.f;

        __syncwarp();
        // ---- perception -> A row (row = tid); channel c -> chunk c>>1, half c&1 ----
        #pragma unroll
        for (int c = 0; c < 21; c++) {
            const float* base = xb + c*HW;
            float n00 = base[hm*WW_ + wm], n01 = base[hm*WW_ + w], n02 = base[hm*WW_ + wp];
            float n10 = base[h*WW_ + wm],  n11 = base[p],          n12 = base[h*WW_ + wp];
            float n20 = base[hp*WW_ + wm], n21 = base[hp*WW_ + w], n22 = base[hp*WW_ + wp];
            float sx = (n02 - n00) + 2.f*(n12 - n10) + (n22 - n20);
            float sy = (n20 - n00) + 2.f*(n21 - n01) + (n22 - n02);
            float lp = n00 + n02 + n20 + n22 + 2.f*(n01 + n10 + n12 + n21) - 12.f*n11;
            uint2 v;
            v.x = pack_bf16(n11, sx);
            v.y = pack_bf16(sy, lp);
            *reinterpret_cast<uint2*>(a_addr(smem, tid, c >> 1, (c & 1) << 3)) = v;
            if (c == 12) g0 = n11;
            if (c == 13) g1 = n11;
            if (c == 14) g2 = n11;
            if (c == 3) {
                float mx = fmaxf(fmaxf(fmaxf(n00, n01), fmaxf(n02, n10)),
                                 fmaxf(fmaxf(n11, n12), fmaxf(fmaxf(n20, n21), n22)));
                life = (mx > 0.1f) ? 1.f : 0.f;
            }
        }
        __syncwarp();

        // ---- fused both-half GEMM: 4 MMA chains share B/w2 loads ----
        {
            const int r0 = warp*32 + w4;        // m=0 rows
            const int r1 = r0 + 8;
            const int r2 = r0 + 16;             // m=1 rows
            const int r3 = r0 + 24;

            uint32_t afr[2][KT6][4];
            #pragma unroll
            for (int k = 0; k < KT6; k++) {
                afr[0][k][0] = *reinterpret_cast<uint32_t*>(a_addr(smem, r0, 2*k,     c4 << 2));
                afr[0][k][1] = *reinterpret_cast<uint32_t*>(a_addr(smem, r1, 2*k,     c4 << 2));
                afr[0][k][2] = *reinterpret_cast<uint32_t*>(a_addr(smem, r0, 2*k + 1, c4 << 2));
                afr[0][k][3] = *reinterpret_cast<uint32_t*>(a_addr(smem, r1, 2*k + 1, c4 << 2));
                afr[1][k][0] = *reinterpret_cast<uint32_t*>(a_addr(smem, r2, 2*k,     c4 << 2));
                afr[1][k][1] = *reinterpret_cast<uint32_t*>(a_addr(smem, r3, 2*k,     c4 << 2));
                afr[1][k][2] = *reinterpret_cast<uint32_t*>(a_addr(smem, r2, 2*k + 1, c4 << 2));
                afr[1][k][3] = *reinterpret_cast<uint32_t*>(a_addr(smem, r3, 2*k + 1, c4 << 2));
            }

            // y[m][rowhalf][3]
            float y00=0.f,y01=0.f,y02=0.f, y10=0.f,y11=0.f,y12=0.f;   // m=0 (r0, r1)
            float y20=0.f,y21=0.f,y22=0.f, y30=0.f,y31=0.f,y32=0.f;   // m=1 (r2, r3)

            #pragma unroll
            for (int np = 0; np < NT/2; np++) {
                const int nA = 2*np, nB = 2*np + 1;
                float cA0=0.f,cA1=0.f,cA2=0.f,cA3=0.f;   // m0 x nA
                float cB0=0.f,cB1=0.f,cB2=0.f,cB3=0.f;   // m0 x nB
                float cC0=0.f,cC1=0.f,cC2=0.f,cC3=0.f;   // m1 x nA
                float cD0=0.f,cD1=0.f,cD2=0.f,cD3=0.f;   // m1 x nB
                const unsigned long long* bpA = bfrag + nA*(KT6*32) + lane;
                #pragma unroll
                for (int k = 0; k < KT6; k++) {
                    unsigned long long bvA = bpA[k*32];
                    unsigned long long bvB = bpA[KT6*32 + k*32];
                    uint32_t bA0 = (uint32_t)bvA, bA1 = (uint32_t)(bvA >> 32);
                    uint32_t bB0 = (uint32_t)bvB, bB1 = (uint32_t)(bvB >> 32);
                    MMA_BF16(cA0,cA1,cA2,cA3, afr[0][k][0],afr[0][k][1],afr[0][k][2],afr[0][k][3], bA0,bA1);
                    MMA_BF16(cB0,cB1,cB2,cB3, afr[0][k][0],afr[0][k][1],afr[0][k][2],afr[0][k][3], bB0,bB1);
                    MMA_BF16(cC0,cC1,cC2,cC3, afr[1][k][0],afr[1][k][1],afr[1][k][2],afr[1][k][3], bA0,bA1);
                    MMA_BF16(cD0,cD1,cD2,cD3, afr[1][k][0],afr[1][k][1],afr[1][k][2],afr[1][k][3], bB0,bB1);
                }
                cA0 = fmaxf(cA0, 0.f); cA1 = fmaxf(cA1, 0.f); cA2 = fmaxf(cA2, 0.f); cA3 = fmaxf(cA3, 0.f);
                cB0 = fmaxf(cB0, 0.f); cB1 = fmaxf(cB1, 0.f); cB2 = fmaxf(cB2, 0.f); cB3 = fmaxf(cB3, 0.f);
                cC0 = fmaxf(cC0, 0.f); cC1 = fmaxf(cC1, 0.f); cC2 = fmaxf(cC2, 0.f); cC3 = fmaxf(cC3, 0.f);
                cD0 = fmaxf(cD0, 0.f); cD1 = fmaxf(cD1, 0.f); cD2 = fmaxf(cD2, 0.f); cD3 = fmaxf(cD3, 0.f);

                int nA0 = 8*nA + 2*c4;
                int nB0 = 8*nB + 2*c4;
                float4 wA = w2s[nA0], wAq = w2s[nA0 + 1];
                float4 wB = w2s[nB0], wBq = w2s[nB0 + 1];

                y00 += wA.x*cA0 + wAq.x*cA1 + wB.x*cB0 + wBq.x*cB1;
                y01 += wA.y*cA0 + wAq.y*cA1 + wB.y*cB0 + wBq.y*cB1;
                y02 += wA.z*cA0 + wAq.z*cA1 + wB.z*cB0 + wBq.z*cB1;
                y10 += wA.x*cA2 + wAq.x*cA3 + wB.x*cB2 + wBq.x*cB3;
                y11 += wA.y*cA2 + wAq.y*cA3 + wB.y*cB2 + wBq.y*cB3;
                y12 += wA.z*cA2 + wAq.z*cA3 + wB.z*cB2 + wBq.z*cB3;
                y20 += wA.x*cC0 + wAq.x*cC1 + wB.x*cD0 + wBq.x*cD1;
                y21 += wA.y*cC0 + wAq.y*cC1 + wB.y*cD0 + wBq.y*cD1;
                y22 += wA.z*cC0 + wAq.z*cC1 + wB.z*cD0 + wBq.z*cD1;
                y30 += wA.x*cC2 + wAq.x*cC3 + wB.x*cD2 + wBq.x*cD3;
                y31 += wA.y*cC2 + wAq.y*cC3 + wB.y*cD2 + wBq.y*cD3;
                y32 += wA.z*cC2 + wAq.z*cC3 + wB.z*cD2 + wBq.z*cD3;
            }

            // quad reduce (lanes sharing w4)
            #define QR(v) v += __shfl_xor_sync(0xFFFFFFFFu, v, 1); v += __shfl_xor_sync(0xFFFFFFFFu, v, 2);
            QR(y00) QR(y01) QR(y02) QR(y10) QR(y11) QR(y12)
            QR(y20) QR(y21) QR(y22) QR(y30) QR(y31) QR(y32)
            #undef QR
            if (c4 == 0) {
                y0buf[r0] = y00; y1buf[r0] = y01; y2buf[r0] = y02;
                y0buf[r1] = y10; y1buf[r1] = y11; y2buf[r1] = y12;
                y0buf[r2] = y20; y1buf[r2] = y21; y2buf[r2] = y22;
                y0buf[r3] = y30; y1buf[r3] = y31; y2buf[r3] = y32;
            }
        }
        __syncwarp();
        float yx = y0buf[tid], yy = y1buf[tid], yz = y2buf[tid];

        float mask = floorf(rn[(size_t)bb*HW + p] + 0.5f);
        float ml = mask * life;
        ob[12*HW + p] = g0 + yx * ml;
        ob[13*HW + p] = g1 + yy * ml;
        ob[14*HW + p] = g2 + yz * ml;
    }
}

// ============================================================
extern "C" void kernel_launch(void* const* d_in, const int* in_sizes, int n_in,
                              void* d_out, int out_size) {
    const float* x     = (const float*)d_in[0];
    const float* rn    = (const float*)d_in[1];
    const float* w1w   = (const float*)d_in[2];
    const float* w1b   = (const float*)d_in[3];
    const float* w2w   = (const float*)d_in[4];
    const float* sloww = (const float*)d_in[5];
    const float* slowb = (const float*)d_in[6];
    const float* modw  = (const float*)d_in[7];
    const float* modb  = (const float*)d_in[8];
    const float* alpha = (const float*)d_in[9];
    const float* beta  = (const float*)d_in[10];
    const float* omega = (const float*)d_in[11];
    const float* K     = (const float*)d_in[12];
    const float* kappa = (const float*)d_in[13];
    float* out = (float*)d_out;

    // one-time resources, created on the (uncaptured) correctness call.
    static int init = 0;
    static int haveFork = 0;
    static cudaStream_t sOsc;
    static cudaEvent_t  eFork, eJoin;
    if (!init) {
        cudaFuncSetAttribute(gene_mlp_mma, cudaFuncAttributeMaxDynamicSharedMemorySize, SM_TOTAL);
        if (cudaStreamCreateWithFlags(&sOsc, cudaStreamNonBlocking) == cudaSuccess &&
            cudaEventCreateWithFlags(&eFork, cudaEventDisableTiming) == cudaSuccess &&
            cudaEventCreateWithFlags(&eJoin, cudaEventDisableTiming) == cudaSuccess) {
            haveFork = 1;
        }
        init = 1;
    }

    dim3 blk(128, 1, 1);
    dim3 grd(WW_/128, HH_, BATCH);
    dim3 grdG(WW_/128, HH_/ROWS_PER_CTA, BATCH);
    dim3 grdP(12*HW/(256*4), BATCH, 1);   // 768 x 16 blocks of 256, float4

    if (haveFork) {
        // fork: oscillator + prefix-copy branch runs concurrently with gene MLP
        cudaEventRecord(eFork, 0);
        cudaStreamWaitEvent(sOsc, eFork, 0);

        prefix_copy<<<grdP, 256, 0, sOsc>>>(x, out);
        osc_step<<<grd, blk, 0, sOsc>>>(x, sloww, slowb, alpha, beta, omega, K, kappa);
        osc_post<<<grd, blk, 0, sOsc>>>(out, modw, modb);
        cudaEventRecord(eJoin, sOsc);

        gene_mlp_mma<<<grdG, blk, SM_TOTAL>>>(x, rn, w1w, w1b, w2w, out);

        // join
        cudaStreamWaitEvent(0, eJoin, 0);
    } else {
        prefix_copy<<<grdP, 256>>>(x, out);
        osc_step<<<grd, blk>>>(x, sloww, slowb, alpha, beta, omega, K, kappa);
        osc_post<<<grd, blk>>>(out, modw, modb);
        gene_mlp_mma<<<grdG, blk, SM_TOTAL>>>(x, rn, w1w, w1b, w2w, out);
    }
}

// round 17
// speedup vs baseline: 1.5351x; 1.5351x over previous
#include <cuda_runtime.h>
#include <cuda_bf16.h>
#include <cstdint>

#define BATCH 16
#define NCH   21
#define HH_   256
#define WW_   256
#define HW    65536
#define CHW   (NCH*HW)
#define DT    0.1f

// GEMM tiling (bf16 m16n8k16): K = 96 (84 feats + bias + 11 zero), N = 96
#define KT6 6          // k16 tiles
#define NT 12          // n8 tiles
#define ROWS_PER_CTA 8

// ---- scratch (allocation-free: __device__ globals) ----
__device__ float g_na[BATCH*HW];
__device__ float g_nb[BATCH*HW];
__device__ float g_nd[BATCH*HW];

__device__ __forceinline__ float lap12(const float v[9]) {
    return (v[0]+v[2]+v[6]+v[8] + 2.f*(v[1]+v[3]+v[5]+v[7]) - 12.f*v[4]) * (1.f/12.f);
}

// ============================================================
// Kernel A: oscillator substep -> scratch new_a/new_b/new_d
// ============================================================
__global__ void osc_step(const float* __restrict__ x,
                         const float* __restrict__ sw, const float* __restrict__ sb,
                         const float* __restrict__ pAlpha, const float* __restrict__ pBeta,
                         const float* __restrict__ pOmega, const float* __restrict__ pK,
                         const float* __restrict__ pKappa) {
    int w = blockIdx.x * 128 + threadIdx.x;
    int h = blockIdx.y;
    int bb = blockIdx.z;
    int p = h * WW_ + w;
    const float* xb = x + (size_t)bb * CHW;

    const bool hu = (h > 0), hd = (h < HH_-1), wl = (w > 0), wr = (w < WW_-1);

    auto L9 = [&](const float* base, float v[9]) {
        const float* r0 = base + (h-1)*WW_;
        const float* r1 = base + h*WW_;
        const float* r2 = base + (h+1)*WW_;
        v[0] = (hu&&wl) ? r0[w-1] : 0.f;
        v[1] = hu       ? r0[w]   : 0.f;
        v[2] = (hu&&wr) ? r0[w+1] : 0.f;
        v[3] = wl       ? r1[w-1] : 0.f;
        v[4] =            r1[w];
        v[5] = wr       ? r1[w+1] : 0.f;
        v[6] = (hd&&wl) ? r2[w-1] : 0.f;
        v[7] = hd       ? r2[w]   : 0.f;
        v[8] = (hd&&wr) ? r2[w+1] : 0.f;
    };

    float va[9];
    L9(xb + 3*HW, va);
    float eroded = va[4];
    if (hu) { eroded = fminf(eroded, va[1]); if (wl) eroded = fminf(eroded, va[0]); if (wr) eroded = fminf(eroded, va[2]); }
    if (wl) eroded = fminf(eroded, va[3]);
    if (wr) eroded = fminf(eroded, va[5]);
    if (hd) { eroded = fminf(eroded, va[7]); if (wl) eroded = fminf(eroded, va[6]); if (wr) eroded = fminf(eroded, va[8]); }
    float lapA = lap12(va);

    float q0 = va[4];
    float q1 = va[4] - eroded;
    float q2 = lapA;
    float q3 = xb[4*HW + p];
    float q4 = xb[5*HW + p];

    float I0 = sw[0]*q0 + sw[1]*q1 + sw[2]*q2 + sw[3]*q3 + sw[4]*q4 + sb[0];
    float I1 = sw[5]*q0 + sw[6]*q1 + sw[7]*q2 + sw[8]*q3 + sw[9]*q4 + sb[1];
    float I2 = sw[10]*q0 + sw[11]*q1 + sw[12]*q2 + sw[13]*q3 + sw[14]*q4 + sb[2];

    float vv[9];
    L9(xb + 15*HW, vv); float av = vv[4], lA = lap12(vv);
    L9(xb + 16*HW, vv); float bv = vv[4], lB = lap12(vv);
    L9(xb + 17*HW, vv); float dv = vv[4], lD = lap12(vv);

    float alpha = pAlpha[0], beta = pBeta[0], omega = pOmega[0], K = pK[0], kap = pKappa[0];

    float na = av + DT * (-alpha*av + omega*bv + K*lA + I0);
    float nb = bv + DT * (-alpha*bv - omega*av + K*lB + I1);
    float nd = dv + DT * (-beta*dv + kap*lD + I2);

    int gi = bb*HW + p;
    g_na[gi] = na; g_nb[gi] = nb; g_nd[gi] = nd;
}

// ============================================================
// Kernel B: avg_pool5 + normalize + correction + phase/amp/mod
// ============================================================
__global__ void osc_post(float* __restrict__ out,
                         const float* __restrict__ mw, const float* __restrict__ mb) {
    int w = blockIdx.x * 128 + threadIdx.x;
    int h = blockIdx.y;
    int bb = blockIdx.z;
    int p = h * WW_ + w;
    int gi = bb*HW + p;

    float sa = 0.f, sb2 = 0.f;
    #pragma unroll
    for (int dy = -2; dy <= 2; dy++) {
        int hh = h + dy;
        if (hh < 0 || hh >= HH_) continue;
        #pragma unroll
        for (int dx = -2; dx <= 2; dx++) {
            int ww = w + dx;
            if (ww < 0 || ww >= WW_) continue;
            int ii = bb*HW + hh*WW_ + ww;
            sa  += g_na[ii];
            sb2 += g_nb[ii];
        }
    }
    float aavg = sa * (1.f/25.f);
    float bavg = sb2 * (1.f/25.f);
    float rho = sqrtf(aavg*aavg + bavg*bavg + 1e-6f);
    aavg /= rho;
    bavg /= rho;

    float na = g_na[gi], nb = g_nb[gi], nd = g_nd[gi];
    float fa = na + DT * (aavg - na);
    float fb = nb + DT * (bavg - nb);

    float phase = sqrtf(fa*fa + fb*fb + 1e-6f);
    float amp = atan2f(fb, fa);

    float m0 = mw[0]*fa + mw[1]*fb + mw[2]*nd + mb[0];
    float m1 = mw[3]*fa + mw[4]*fb + mw[5]*nd + mb[1];
    float m2 = mw[6]*fa + mw[7]*fb + mw[8]*nd + mb[2];

    float* ob = out + (size_t)bb * CHW;
    ob[15*HW + p] = fa;
    ob[16*HW + p] = fb;
    ob[17*HW + p] = nd;
    ob[18*HW + p] = m0;
    ob[19*HW + p] = m1;
    ob[20*HW + p] = m2;

    float* phaseOut = out + (size_t)BATCH * CHW;
    float* ampOut   = phaseOut + (size_t)BATCH * HW;
    phaseOut[gi] = phase;
    ampOut[gi]   = amp;
}

// ============================================================
// Kernel C: perception (wrap) + bf16 MMA MLP with back-to-back
// second GEMM for the W2 epilogue (C-frag -> A-frag reuse)
// ============================================================
__device__ __forceinline__ uint32_t pack_bf16(float lo, float hi) {
    uint32_t r;
    asm("cvt.rn.bf16x2.f32 %0, %1, %2;" : "=r"(r) : "f"(hi), "f"(lo));
    return r;
}

#define MMA_BF16(c0,c1,c2,c3, a0,a1,a2,a3, b0,b1) \
    asm volatile("mma.sync.aligned.m16n8k16.row.col.f32.bf16.bf16.f32 " \
        "{%0,%1,%2,%3}, {%4,%5,%6,%7}, {%8,%9}, {%0,%1,%2,%3};" \
        : "+f"(c0), "+f"(c1), "+f"(c2), "+f"(c3) \
        : "r"(a0), "r"(a1), "r"(a2), "r"(a3), "r"(b0), "r"(b1))

// dynamic SMEM layout (bytes)
#define SM_BFRAG 0                       // NT*KT6*32 u64 = 18432
#define SM_B2    18432                   // KT6*32 u64 = 1536 (W2^T fragments)
#define SM_Y0    19968                   // 128 float = 512
#define SM_Y1    20480                   // 128 float = 512
#define SM_Y2    20992                   // 128 float = 512
#define SM_A     21504                   // 128 rows x 192B, mod-12 swizzle
#define A_STRIDE 192
#define SM_TOTAL (SM_A + 128*A_STRIDE)   // 46080 = 45KB -> 5 CTAs/SM

// A tile: row r, 16B chunk c in [0,12), byte off within chunk.
// swizzle: sw = (c + 3*((r>>1)&3)) mod 12  -> conflict-free within 8-row groups
__device__ __forceinline__ char* a_addr(char* smem, int r, int c, int byteoff) {
    int swc = c + 3*((r >> 1) & 3);
    swc = (swc >= 12) ? swc - 12 : swc;
    return smem + SM_A + r*A_STRIDE + (swc << 4) + byteoff;
}

// feature row -> w1 source value
__device__ __forceinline__ float w1_feat(const float* __restrict__ w1w,
                                         const float* __restrict__ w1b,
                                         int col, int r) {
    if (r < 84) {
        int cc = r >> 2, j = r & 3;
        return w1w[col*84 + (j == 0 ? cc : 21 + 3*cc + (j-1))];
    }
    return (r == 84) ? w1b[col] : 0.f;
}

__global__ void __launch_bounds__(128, 5) gene_mlp_mma(
    const float* __restrict__ x, const float* __restrict__ rn,
    const float* __restrict__ w1w, const float* __restrict__ w1b,
    const float* __restrict__ w2w, float* __restrict__ out) {

    extern __shared__ __align__(128) char smem[];
    unsigned long long* bfrag  = reinterpret_cast<unsigned long long*>(smem + SM_BFRAG);
    unsigned long long* bfrag2 = reinterpret_cast<unsigned long long*>(smem + SM_B2);
    float* y0buf = reinterpret_cast<float*>(smem + SM_Y0);
    float* y1buf = reinterpret_cast<float*>(smem + SM_Y1);
    float* y2buf = reinterpret_cast<float*>(smem + SM_Y2);

    const int tid  = threadIdx.x;
    const int lane = tid & 31;
    const int warp = tid >> 5;
    const int w4   = lane >> 2;   // 0..7
    const int c4   = lane & 3;    // 0..3

    // ---- stage B (W1) fragments once per CTA ----
    for (int i = tid; i < NT*KT6*32; i += 128) {
        int n   = i / (KT6*32);
        int rem = i - n*(KT6*32);
        int k   = rem >> 5;
        int l   = rem & 31;
        int col = 8*n + (l >> 2);
        int kb  = 16*k + 2*(l & 3);
        uint32_t lo = pack_bf16(w1_feat(w1w, w1b, col, kb),
                                w1_feat(w1w, w1b, col, kb + 1));
        uint32_t hi = pack_bf16(w1_feat(w1w, w1b, col, kb + 8),
                                w1_feat(w1w, w1b, col, kb + 9));
        bfrag[i] = (unsigned long long)lo | ((unsigned long long)hi << 32);
    }
    // ---- stage B2 (W2^T, k=96 hidden x n=8 [cols 0..2 real]) fragments ----
    for (int i = tid; i < KT6*32; i += 128) {
        int kt = i >> 5;
        int l  = i & 31;
        int j  = l >> 2;                 // output col 0..7
        int k0 = 16*kt + 2*(l & 3);
        float v0 = (j < 3) ? w2w[j*96 + k0]     : 0.f;
        float v1 = (j < 3) ? w2w[j*96 + k0 + 1] : 0.f;
        float v2 = (j < 3) ? w2w[j*96 + k0 + 8] : 0.f;
        float v3 = (j < 3) ? w2w[j*96 + k0 + 9] : 0.f;
        uint32_t lo = pack_bf16(v0, v1);
        uint32_t hi = pack_bf16(v2, v3);
        bfrag2[i] = (unsigned long long)lo | ((unsigned long long)hi << 32);
    }

    // constant A columns: chunk 10 half1 = (bias=1, 0, 0, 0); chunk 11 = zeros
    {
        uint2 bz; bz.x = pack_bf16(1.f, 0.f); bz.y = pack_bf16(0.f, 0.f);
        *reinterpret_cast<uint2*>(a_addr(smem, tid, 10, 8)) = bz;
        uint2 zz; zz.x = 0u; zz.y = 0u;
        *reinterpret_cast<uint2*>(a_addr(smem, tid, 11, 0)) = zz;
        *reinterpret_cast<uint2*>(a_addr(smem, tid, 11, 8)) = zz;
    }
    __syncthreads();

    const int w  = blockIdx.x * 128 + tid;
    const int bb = blockIdx.z;
    const float* xb = x + (size_t)bb * CHW;
    float* ob = out + (size_t)bb * CHW;

    #pragma unroll 1
    for (int t = 0; t < ROWS_PER_CTA; t++) {
        const int h  = blockIdx.y * ROWS_PER_CTA + t;
        const int hm = (h - 1) & 255, hp = (h + 1) & 255;
        const int wm = (w - 1) & 255, wp = (w + 1) & 255;
        const int p  = h * WW_ + w;

        float g0 = 0.f, g1 = 0.f, g2 = 0.f, life = 0.f;

        __syncwarp();
        // ---- perception -> A row (row = tid); channel c -> chunk c>>1, half c&1 ----
        #pragma unroll
        for (int c = 0; c < 21; c++) {
            const float* base = xb + c*HW;
            float n00 = base[hm*WW_ + wm], n01 = base[hm*WW_ + w], n02 = base[hm*WW_ + wp];
            float n10 = base[h*WW_ + wm],  n11 = base[p],          n12 = base[h*WW_ + wp];
            float n20 = base[hp*WW_ + wm], n21 = base[hp*WW_ + w], n22 = base[hp*WW_ + wp];
            float sx = (n02 - n00) + 2.f*(n12 - n10) + (n22 - n20);
            float sy = (n20 - n00) + 2.f*(n21 - n01) + (n22 - n02);
            float lp = n00 + n02 + n20 + n22 + 2.f*(n01 + n10 + n12 + n21) - 12.f*n11;
            uint2 v;
            v.x = pack_bf16(n11, sx);
            v.y = pack_bf16(sy, lp);
            *reinterpret_cast<uint2*>(a_addr(smem, tid, c >> 1, (c & 1) << 3)) = v;
            if (c < 12)  ob[c*HW + p] = n11;
            if (c == 12) g0 = n11;
            if (c == 13) g1 = n11;
            if (c == 14) g2 = n11;
            if (c == 3) {
                float mx = fmaxf(fmaxf(fmaxf(n00, n01), fmaxf(n02, n10)),
                                 fmaxf(fmaxf(n11, n12), fmaxf(fmaxf(n20, n21), n22)));
                life = (mx > 0.1f) ? 1.f : 0.f;
            }
        }
        __syncwarp();

        // ---- fused both-half GEMM1 + back-to-back GEMM2 (W2) ----
        {
            const int r0 = warp*32 + w4;        // m=0 rows
            const int r1 = r0 + 8;
            const int r2 = r0 + 16;             // m=1 rows
            const int r3 = r0 + 24;

            uint32_t afr[2][KT6][4];
            #pragma unroll
            for (int k = 0; k < KT6; k++) {
                afr[0][k][0] = *reinterpret_cast<uint32_t*>(a_addr(smem, r0, 2*k,     c4 << 2));
                afr[0][k][1] = *reinterpret_cast<uint32_t*>(a_addr(smem, r1, 2*k,     c4 << 2));
                afr[0][k][2] = *reinterpret_cast<uint32_t*>(a_addr(smem, r0, 2*k + 1, c4 << 2));
                afr[0][k][3] = *reinterpret_cast<uint32_t*>(a_addr(smem, r1, 2*k + 1, c4 << 2));
                afr[1][k][0] = *reinterpret_cast<uint32_t*>(a_addr(smem, r2, 2*k,     c4 << 2));
                afr[1][k][1] = *reinterpret_cast<uint32_t*>(a_addr(smem, r3, 2*k,     c4 << 2));
                afr[1][k][2] = *reinterpret_cast<uint32_t*>(a_addr(smem, r2, 2*k + 1, c4 << 2));
                afr[1][k][3] = *reinterpret_cast<uint32_t*>(a_addr(smem, r3, 2*k + 1, c4 << 2));
            }

            // GEMM2 accumulators (C2 frags per m-half)
            float z00=0.f,z01=0.f,z02=0.f,z03=0.f;   // m=0
            float z10=0.f,z11=0.f,z12=0.f,z13=0.f;   // m=1

            #pragma unroll
            for (int np = 0; np < NT/2; np++) {
                const int nA = 2*np, nB = 2*np + 1;
                float cA0=0.f,cA1=0.f,cA2=0.f,cA3=0.f;   // m0 x nA
                float cB0=0.f,cB1=0.f,cB2=0.f,cB3=0.f;   // m0 x nB
                float cC0=0.f,cC1=0.f,cC2=0.f,cC3=0.f;   // m1 x nA
                float cD0=0.f,cD1=0.f,cD2=0.f,cD3=0.f;   // m1 x nB
                const unsigned long long* bpA = bfrag + nA*(KT6*32) + lane;
                #pragma unroll
                for (int k = 0; k < KT6; k++) {
                    unsigned long long bvA = bpA[k*32];
                    unsigned long long bvB = bpA[KT6*32 + k*32];
                    uint32_t bA0 = (uint32_t)bvA, bA1 = (uint32_t)(bvA >> 32);
                    uint32_t bB0 = (uint32_t)bvB, bB1 = (uint32_t)(bvB >> 32);
                    MMA_BF16(cA0,cA1,cA2,cA3, afr[0][k][0],afr[0][k][1],afr[0][k][2],afr[0][k][3], bA0,bA1);
                    MMA_BF16(cB0,cB1,cB2,cB3, afr[0][k][0],afr[0][k][1],afr[0][k][2],afr[0][k][3], bB0,bB1);
                    MMA_BF16(cC0,cC1,cC2,cC3, afr[1][k][0],afr[1][k][1],afr[1][k][2],afr[1][k][3], bA0,bA1);
                    MMA_BF16(cD0,cD1,cD2,cD3, afr[1][k][0],afr[1][k][1],afr[1][k][2],afr[1][k][3], bB0,bB1);
                }
                // relu, then repack C frags as A2 frags of k16-tile np
                cA0 = fmaxf(cA0, 0.f); cA1 = fmaxf(cA1, 0.f); cA2 = fmaxf(cA2, 0.f); cA3 = fmaxf(cA3, 0.f);
                cB0 = fmaxf(cB0, 0.f); cB1 = fmaxf(cB1, 0.f); cB2 = fmaxf(cB2, 0.f); cB3 = fmaxf(cB3, 0.f);
                cC0 = fmaxf(cC0, 0.f); cC1 = fmaxf(cC1, 0.f); cC2 = fmaxf(cC2, 0.f); cC3 = fmaxf(cC3, 0.f);
                cD0 = fmaxf(cD0, 0.f); cD1 = fmaxf(cD1, 0.f); cD2 = fmaxf(cD2, 0.f); cD3 = fmaxf(cD3, 0.f);

                unsigned long long b2v = bfrag2[np*32 + lane];
                uint32_t b20 = (uint32_t)b2v, b21 = (uint32_t)(b2v >> 32);

                uint32_t a20 = pack_bf16(cA0, cA1);
                uint32_t a21 = pack_bf16(cA2, cA3);
                uint32_t a22 = pack_bf16(cB0, cB1);
                uint32_t a23 = pack_bf16(cB2, cB3);
                MMA_BF16(z00,z01,z02,z03, a20,a21,a22,a23, b20,b21);

                a20 = pack_bf16(cC0, cC1);
                a21 = pack_bf16(cC2, cC3);
                a22 = pack_bf16(cD0, cD1);
                a23 = pack_bf16(cD2, cD3);
                MMA_BF16(z10,z11,z12,z13, a20,a21,a22,a23, b20,b21);
            }

            // C2 frag: lane holds (row r, col 2*c4),(row r, col 2*c4+1),(row r+8, ...)
            // cols 0,1 live in c4==0 lanes; col 2 lives in c4==1 lanes.
            if (c4 == 0) {
                y0buf[r0] = z00; y1buf[r0] = z01;
                y0buf[r1] = z02; y1buf[r1] = z03;
                y0buf[r2] = z10; y1buf[r2] = z11;
                y0buf[r3] = z12; y1buf[r3] = z13;
            }
            if (c4 == 1) {
                y2buf[r0] = z00;
                y2buf[r1] = z02;
                y2buf[r2] = z10;
                y2buf[r3] = z12;
            }
        }
        __syncwarp();
        float yx = y0buf[tid], yy = y1buf[tid], yz = y2buf[tid];

        float mask = floorf(rn[(size_t)bb*HW + p] + 0.5f);
        float ml = mask * life;
        ob[12*HW + p] = g0 + yx * ml;
        ob[13*HW + p] = g1 + yy * ml;
        ob[14*HW + p] = g2 + yz * ml;
    }
}

// ============================================================
extern "C" void kernel_launch(void* const* d_in, const int* in_sizes, int n_in,
                              void* d_out, int out_size) {
    const float* x     = (const float*)d_in[0];
    const float* rn    = (const float*)d_in[1];
    const float* w1w   = (const float*)d_in[2];
    const float* w1b   = (const float*)d_in[3];
    const float* w2w   = (const float*)d_in[4];
    const float* sloww = (const float*)d_in[5];
    const float* slowb = (const float*)d_in[6];
    const float* modw  = (const float*)d_in[7];
    const float* modb  = (const float*)d_in[8];
    const float* alpha = (const float*)d_in[9];
    const float* beta  = (const float*)d_in[10];
    const float* omega = (const float*)d_in[11];
    const float* K     = (const float*)d_in[12];
    const float* kappa = (const float*)d_in[13];
    float* out = (float*)d_out;

    // one-time resources, created on the (uncaptured) correctness call.
    static int init = 0;
    static int haveFork = 0;
    static cudaStream_t sOsc;
    static cudaEvent_t  eFork, eJoin;
    if (!init) {
        cudaFuncSetAttribute(gene_mlp_mma, cudaFuncAttributeMaxDynamicSharedMemorySize, SM_TOTAL);
        if (cudaStreamCreateWithFlags(&sOsc, cudaStreamNonBlocking) == cudaSuccess &&
            cudaEventCreateWithFlags(&eFork, cudaEventDisableTiming) == cudaSuccess &&
            cudaEventCreateWithFlags(&eJoin, cudaEventDisableTiming) == cudaSuccess) {
            haveFork = 1;
        }
        init = 1;
    }

    dim3 blk(128, 1, 1);
    dim3 grd(WW_/128, HH_, BATCH);
    dim3 grdG(WW_/128, HH_/ROWS_PER_CTA, BATCH);

    if (haveFork) {
        // fork: oscillator branch runs concurrently with the gene MLP branch
        cudaEventRecord(eFork, 0);
        cudaStreamWaitEvent(sOsc, eFork, 0);

        osc_step<<<grd, blk, 0, sOsc>>>(x, sloww, slowb, alpha, beta, omega, K, kappa);
        osc_post<<<grd, blk, 0, sOsc>>>(out, modw, modb);
        cudaEventRecord(eJoin, sOsc);

        gene_mlp_mma<<<grdG, blk, SM_TOTAL>>>(x, rn, w1w, w1b, w2w, out);

        // join
        cudaStreamWaitEvent(0, eJoin, 0);
    } else {
        osc_step<<<grd, blk>>>(x, sloww, slowb, alpha, beta, omega, K, kappa);
        osc_post<<<grd, blk>>>(out, modw, modb);
        gene_mlp_mma<<<grdG, blk, SM_TOTAL>>>(x, rn, w1w, w1b, w2w, out);
    }
}